// round 10
// baseline (speedup 1.0000x reference)
#include <cuda_runtime.h>

// Pair_83811991814342
// in:  (1, 1024, 260) fp32; only first 512 rows used
// out: (1, 512*512, 522) fp32 : [x[i](260) | x[j](260) | r1 | r2]
// Output row = 2088 B (== 8 mod 16): even rows 16B-aligned, odd rows 8-shifted.
// STG.128 everywhere; 8x16 tile for 33KB contiguous write bursts.

#define NROWS 512
#define DIM   260
#define TI    8
#define TJ    16
#define NT    288
#define RSTR  264                    // smem row stride in floats (1056 B)
#define ROWB  ((2 * DIM + 2) * 4)    // 2088 output bytes per row

__global__ __launch_bounds__(NT)
void pair_kernel(const float* __restrict__ in, float* __restrict__ out) {
    __shared__ float  s_rows[TI + TJ][RSTR];  // rows 0-7: i-rows, 8-23: j-rows
    __shared__ float2 s_r[TI * TJ];           // (r1, r2) per (il, jl)

    const int bi = blockIdx.y * TI;
    const int bj = blockIdx.x * TJ;
    const int t  = threadIdx.x;

    // ---- Stage the 24 source rows into smem (float4 vectorized) ----
    for (int u = t; u < (TI + TJ) * 65; u += NT) {
        int r = u / 65;
        int q = u - r * 65;
        int g = (r < TI) ? (bi + r) : (bj + (r - TI));
        *reinterpret_cast<float4*>(&s_rows[r][4 * q]) =
            __ldg(reinterpret_cast<const float4*>(in + g * DIM) + q);
    }

    // ---- Threads 0..127: (r1, r2) table ----
    if (t < TI * TJ) {
        int il = t >> 4, jl = t & 15;
        const float4 a = __ldg(reinterpret_cast<const float4*>(
            in + (bi + il) * DIM + (DIM - 4)));
        const float4 b = __ldg(reinterpret_cast<const float4*>(
            in + (bj + jl) * DIM + (DIM - 4)));
        float w = fmaxf(0.0f, fminf(a.z, b.z) - fmaxf(a.x, b.x));
        float h = fmaxf(0.0f, fminf(a.w, b.w) - fmaxf(a.y, b.y));
        float inter = w * h;
        s_r[t] = make_float2(inter / ((a.z - a.x) * (a.w - a.y)),
                             inter / ((b.z - b.x) * (b.w - b.y)));
    }
    __syncthreads();

    if (t >= 262) return;
    const int c   = (t < 131) ? t : t - 131;   // quad column [0,131)
    const int il0 = (t < 131) ? 0 : 4;         // il half

    char* const obBase = reinterpret_cast<char*>(out)
                       + (size_t)(bi * NROWS + bj) * ROWB;
    const char* const srow  = reinterpret_cast<const char*>(&s_rows[0][0]);
    const char* const sjrow = srow + TI * (RSTR * 4);
    const char* const srr   = reinterpret_cast<const char*>(&s_r[0]);

    if (c < 130) {
        // EVEN rows: quad c = output floats [4c, 4c+4)
        const char* sE; int stEi, stEj;
        if (c < 65) { sE = srow  + 16 * c;        stEi = RSTR * 4; stEj = 0; }
        else        { sE = sjrow + 16 * (c - 65); stEi = 0;        stEj = RSTR * 4; }
        // ODD rows: quad c = floats [4c+2, 4c+6) = lo2 + hi2
        const char* sL; int stLi, stLj;
        if (c < 65) { sL = srow  + 16 * c + 8;        stLi = RSTR * 4; stLj = 0; }
        else        { sL = sjrow + 16 * (c - 65) + 8; stLi = 0;        stLj = RSTR * 4; }
        const char* sH; int stHi, stHj;
        if (c < 64)       { sH = srow  + 16 * c + 16;        stHi = RSTR * 4; stHj = 0; }
        else if (c == 64) { sH = sjrow;                      stHi = 0;        stHj = RSTR * 4; }
        else if (c < 129) { sH = sjrow + 16 * (c - 65) + 16; stHi = 0;        stHj = RSTR * 4; }
        else              { sH = srr;                        stHi = TJ * 8;   stHj = 8; } // (r1,r2)

        char* const obE = obBase + 16 * c;       // even rows: 16B-aligned
        char* const obO = obBase + 16 * c + 8;   // odd rows: +8 -> 16B-aligned

        #pragma unroll
        for (int k = 0; k < 4; k++) {
            const int il = il0 + k;
            #pragma unroll
            for (int jl = 0; jl < TJ; jl++) {
                const size_t off = (size_t)(il * NROWS + jl) * ROWB;
                if ((jl & 1) == 0) {
                    *reinterpret_cast<float4*>(obE + off) =
                        *reinterpret_cast<const float4*>(sE + il * stEi + jl * stEj);
                } else {
                    float2 lo = *reinterpret_cast<const float2*>(sL + il * stLi + jl * stLj);
                    float2 hi = *reinterpret_cast<const float2*>(sH + il * stHi + jl * stHj);
                    *reinterpret_cast<float4*>(obO + off) =
                        make_float4(lo.x, lo.y, hi.x, hi.y);
                }
            }
        }
    } else {
        // c == 130: even rows -> tail (r1,r2) at byte 2080; odd rows -> head x[i][0:2]
        #pragma unroll
        for (int k = 0; k < 4; k++) {
            const int il = il0 + k;
            #pragma unroll
            for (int jl = 0; jl < TJ; jl++) {
                const size_t off = (size_t)(il * NROWS + jl) * ROWB;
                if ((jl & 1) == 0) {
                    *reinterpret_cast<float2*>(obBase + off + 2080) = s_r[il * TJ + jl];
                } else {
                    *reinterpret_cast<float2*>(obBase + off) =
                        *reinterpret_cast<const float2*>(srow + il * (RSTR * 4));
                }
            }
        }
    }
}

extern "C" void kernel_launch(void* const* d_in, const int* in_sizes, int n_in,
                              void* d_out, int out_size) {
    const float* in = (const float*)d_in[0];
    float* out = (float*)d_out;
    dim3 grid(NROWS / TJ, NROWS / TI);  // 32 x 64 blocks
    pair_kernel<<<grid, NT>>>(in, out);
}